// round 12
// baseline (speedup 1.0000x reference)
#include <cuda_runtime.h>
#include <cuda_fp16.h>
#include <cstdint>

// ============================================================
// x(16384,128) f32, p(16384,8) f32, W(128,4096) f32, b(4096) f32
// logits[b,n] = sum_f x[b,f]*W[f,n],  n = c*512 + d*64 + r
// out[b, d*64+r] = sum_c p[b,c] * softmax_d(logits[b,c,:,r])
//
// R12: single-term fp16 mma.sync, columns permuted n'=r*64+c*8+d.
// 2 CTAs per SM (grid 256 = 128 rowblocks x 2 n-halves) so two
// independent barrier domains drift into anti-phase: one CTA's
// MMA overlaps the other's MUFU epilogue. CTA = 128 rows x 2048
// cols, W streamed as 64-col chunks (16KB, double-buffered),
// 8 warps x 16 rows x 64 cols -> softmax AND p-sum warp-local.
// ============================================================

#define NF 128

// -------- device scratch --------
__device__ __align__(1024) uint8_t g_Wh[32u * 32768];   // [slab][kh][256n][8ch][16B]
__device__ __align__(1024) uint8_t g_Xh[128u * 32768];  // [rowblk][128r][16ch][16B]
__device__ __align__(16) float g_biasp[4096];

// -------- smem byte offsets (per CTA, 108 KB) --------
#define SM_XH    0                 // 32768
#define SM_W     32768             // 2 x 16384 chunk buffers
#define SM_BIAS  65536             // 8192 (this CTA's 2048 cols)
#define SM_STAGE 73728             // 2 x 16384 (one slab = 4 chunks each)
#define SM_P     106496            // 4096
#define SM_TOT   110592

__device__ __forceinline__ uint32_t smem_u32(const void* p) {
    return (uint32_t)__cvta_generic_to_shared(p);
}
__device__ __forceinline__ void cp16(uint32_t dst, const void* src) {
    asm volatile("cp.async.cg.shared.global [%0], [%1], 16;" :: "r"(dst), "l"(src));
}
#define LDSM4(r, a) \
    asm volatile("ldmatrix.sync.aligned.m8n8.x4.shared.b16 {%0,%1,%2,%3}, [%4];" \
        : "=r"((r)[0]), "=r"((r)[1]), "=r"((r)[2]), "=r"((r)[3]) : "r"(a))

__device__ __forceinline__ void mma16816h(float* c, const uint32_t* a,
                                          uint32_t b0, uint32_t b1) {
    asm volatile(
        "mma.sync.aligned.m16n8k16.row.col.f32.f16.f16.f32 "
        "{%0,%1,%2,%3}, {%4,%5,%6,%7}, {%8,%9}, {%0,%1,%2,%3};"
        : "+f"(c[0]), "+f"(c[1]), "+f"(c[2]), "+f"(c[3])
        : "r"(a[0]), "r"(a[1]), "r"(a[2]), "r"(a[3]), "r"(b0), "r"(b1));
}
__device__ __forceinline__ uint32_t pack2h(float a, float b) {
    __half2 h;
    h.x = __float2half_rn(a);
    h.y = __float2half_rn(b);
    return *reinterpret_cast<uint32_t*>(&h);
}

// ============================================================
// Merged prep: W -> permuted fp16 image; x -> fp16 image;
// bias -> permuted. (unchanged, validated R8-R11)
// ============================================================
__global__ void prep_kernel(const float* __restrict__ X,
                            const float* __restrict__ W,
                            const float* __restrict__ bias) {
    int idx = blockIdx.x * 256 + threadIdx.x;   // 0 .. 1048575

    if (idx < 4096) {
        int n = idx;
        int c = n >> 9, d = (n >> 6) & 7, r = n & 63;
        g_biasp[r * 64 + c * 8 + d] = bias[n];
    }

    if (idx < 64 * 4096) {                      // W items
        int f2 = (idx >> 12) * 2;
        int n  = idx & 4095;
        float w0 = W[(size_t)f2 * 4096 + n];
        float w1 = W[(size_t)(f2 + 1) * 4096 + n];
        int c = n >> 9, d = (n >> 6) & 7, r = n & 63;
        int np = r * 64 + c * 8 + d;            // permuted column
        int slab = np >> 8, nl = np & 255;
        int kh = f2 >> 6, kl = f2 & 63;
        int ch = kl >> 3;
        uint32_t off = (uint32_t)(nl * 128 + (((ch ^ (nl & 7)) & 7) << 4) + (kl & 7) * 2);
        *(uint32_t*)(g_Wh + ((size_t)slab * 2 + kh) * 32768 + off) = pack2h(w0, w1);
    }

    {
        int row = idx >> 6;
        int k2  = (idx & 63) * 2;
        float2 v = *reinterpret_cast<const float2*>(X + (size_t)row * NF + k2);
        int blk = row >> 7, rl = row & 127;
        int ch = k2 >> 3;
        uint32_t off = (uint32_t)(rl * 256 + ((ch ^ (rl & 7)) << 4) + (k2 & 7) * 2);
        *(uint32_t*)(g_Xh + (size_t)blk * 32768 + off) = pack2h(v.x, v.y);
    }
}

// fetch one 64-col W chunk (16 KB: kh=0 and kh=1 8KB blocks)
__device__ __forceinline__ void fetch_chunk(uint32_t dstbuf, int cg, int tid) {
    const uint8_t* base = g_Wh + (size_t)(cg >> 2) * 65536 + (size_t)(cg & 3) * 8192;
    #pragma unroll
    for (int i = 0; i < 4; i++) {
        int idx = tid + i * 256;                // float4 index 0..1023
        int kh = idx >> 9, rem = idx & 511;
        cp16(dstbuf + kh * 8192 + rem * 16, base + kh * 32768 + rem * 16);
    }
    asm volatile("cp.async.commit_group;");
}

// ============================================================
// Main kernel: 256 CTAs x 256 threads, 2 CTAs/SM.
// CTA = rows [rowblk*128, +128) x permuted cols [nhalf*2048, +2048)
// warp w covers rows [w*16, +16) x all 64 cols of each chunk.
// ============================================================
__global__ __launch_bounds__(256, 2)
void crowds_mma_kernel(const float* __restrict__ p, float* __restrict__ out) {
    extern __shared__ __align__(1024) uint8_t smem[];
    const uint32_t sb = smem_u32(smem);
    float* biasS = (float*)(smem + SM_BIAS);
    float* psS   = (float*)(smem + SM_P);

    const int tid = threadIdx.x, lane = tid & 31, warp = tid >> 5;
    const int rowblk = blockIdx.x >> 1, nhalf = blockIdx.x & 1;
    const int rowbase = rowblk * 128;
    const int cg0 = nhalf * 32;                 // first global chunk (= r) index

    // ---- prologue: X image, W chunk 0, bias half (one group); p ----
    {
        const uint8_t* gx = g_Xh + (size_t)rowblk * 32768;
        #pragma unroll
        for (int i = 0; i < 8; i++) {
            int o = (tid + i * 256) * 16;
            cp16(sb + SM_XH + o, gx + o);
        }
        #pragma unroll
        for (int i = 0; i < 2; i++) {
            int o = (tid + i * 256) * 16;
            cp16(sb + SM_BIAS + o, (const uint8_t*)(g_biasp + nhalf * 2048) + o);
        }
        asm volatile("cp.async.commit_group;");
        fetch_chunk(sb + SM_W, cg0, tid);
        #pragma unroll
        for (int i = 0; i < 4; i++) {
            int ii = tid + i * 256;
            int row = ii >> 3, c = ii & 7;
            psS[c * 128 + row] = p[(size_t)(rowbase + row) * 8 + c];
        }
    }

    const int q = lane & 3, rowq = lane >> 2;
    const int arow = warp * 16 + (lane & 7) + ((lane >> 3) & 1) * 8;
    const int bnl  = (lane & 7) + ((lane >> 4) << 3);   // + g*16
    const int row0 = warp * 16 + rowq;

    for (int cl = 0; cl < 32; cl++) {
        asm volatile("cp.async.wait_group 0;");
        __syncthreads();

        // prefetch next chunk (overlaps this chunk's MMA+epilogue)
        if (cl + 1 < 32)
            fetch_chunk(sb + SM_W + ((cl + 1) & 1) * 16384, cg0 + cl + 1, tid);

        // deferred coalesced stores of previous completed slab
        if (cl > 0 && (cl & 3) == 0) {
            const int sl_prev = (cl >> 2) - 1;
            const int slab_abs = nhalf * 8 + sl_prev;
            const float* stg = (const float*)(smem + SM_STAGE + (sl_prev & 1) * 16384);
            #pragma unroll
            for (int w = 0; w < 4; w++) {
                int i = tid + w * 256;
                int row = i >> 3, d = i & 7;
                float4 v = *(const float4*)&stg[row * 32 + d * 4];
                *(float4*)&out[(size_t)(rowbase + row) * 512 + d * 64 + slab_abs * 4] = v;
            }
        }

        // ---- MMA: this warp's 16 rows x 64 cols, K=128 ----
        float acc[4][2][4];
        #pragma unroll
        for (int g = 0; g < 4; g++)
            #pragma unroll
            for (int hf = 0; hf < 2; hf++)
                #pragma unroll
                for (int e = 0; e < 4; e++) acc[g][hf][e] = 0.f;

        const uint32_t wbuf = sb + SM_W + (cl & 1) * 16384;
        #pragma unroll
        for (int ks8 = 0; ks8 < 8; ks8++) {
            uint32_t ah[4];
            const int xch = ks8 * 2 + (lane >> 4);
            uint32_t aoff = (uint32_t)(arow * 256 + ((xch ^ (arow & 7)) << 4));
            LDSM4(ah, sb + SM_XH + aoff);
            const int bch = (ks8 & 3) * 2 + ((lane >> 3) & 1);
            #pragma unroll
            for (int g = 0; g < 4; g++) {
                uint32_t bh[4];
                const int nloc = bnl + g * 16;
                uint32_t boff = (uint32_t)((ks8 >> 2) * 8192 + nloc * 128
                                           + (((bch ^ (nloc & 7)) & 7) << 4));
                LDSM4(bh, wbuf + boff);
                mma16816h(&acc[g][0][0], ah, bh[0], bh[1]);
                mma16816h(&acc[g][1][0], ah, bh[2], bh[3]);
            }
        }

        // ---- epilogue: softmax over d (quad shuffles) + p-sum over c ----
        // chunk = one r value; groups x hf enumerate c = 0..7.
        float of[4] = {0.f, 0.f, 0.f, 0.f};
        #pragma unroll
        for (int g = 0; g < 4; g++) {
            #pragma unroll
            for (int hf = 0; hf < 2; hf++) {
                const int c = g * 2 + hf;
                float2 bv = *(const float2*)&biasS[cl * 64 + c * 8 + q * 2];
                const float* a4 = &acc[g][hf][0];
                float e0 = __expf(a4[0] + bv.x);
                float e1 = __expf(a4[1] + bv.y);
                float e2 = __expf(a4[2] + bv.x);
                float e3 = __expf(a4[3] + bv.y);
                float s0 = e0 + e1, s1 = e2 + e3;
                s0 += __shfl_xor_sync(0xffffffffu, s0, 1);
                s0 += __shfl_xor_sync(0xffffffffu, s0, 2);
                s1 += __shfl_xor_sync(0xffffffffu, s1, 1);
                s1 += __shfl_xor_sync(0xffffffffu, s1, 2);
                float f0 = __fdividef(psS[c * 128 + row0], s0);
                float f1 = __fdividef(psS[c * 128 + row0 + 8], s1);
                of[0] = fmaf(e0, f0, of[0]);
                of[1] = fmaf(e1, f0, of[1]);
                of[2] = fmaf(e2, f1, of[2]);
                of[3] = fmaf(e3, f1, of[3]);
            }
        }

        // ---- write into slab stage (rl-th column set of the slab) ----
        {
            const int rl = cl & 3;
            float* stage = (float*)(smem + SM_STAGE + ((cl >> 2) & 1) * 16384);
            stage[row0 * 32 + (2 * q) * 4 + rl]           = of[0];
            stage[row0 * 32 + (2 * q + 1) * 4 + rl]       = of[1];
            stage[(row0 + 8) * 32 + (2 * q) * 4 + rl]     = of[2];
            stage[(row0 + 8) * 32 + (2 * q + 1) * 4 + rl] = of[3];
        }
    }

    // ---- final stores: slab 7 (stage buffer 1) ----
    __syncthreads();
    {
        const int slab_abs = nhalf * 8 + 7;
        const float* stg = (const float*)(smem + SM_STAGE + 16384);
        #pragma unroll
        for (int w = 0; w < 4; w++) {
            int i = tid + w * 256;
            int row = i >> 3, d = i & 7;
            float4 v = *(const float4*)&stg[row * 32 + d * 4];
            *(float4*)&out[(size_t)(rowbase + row) * 512 + d * 64 + slab_abs * 4] = v;
        }
    }
}

// ============================================================
extern "C" void kernel_launch(void* const* d_in, const int* in_sizes, int n_in,
                              void* d_out, int out_size) {
    const float* x    = (const float*)d_in[0];
    const float* p    = (const float*)d_in[1];
    const float* W    = (const float*)d_in[2];
    const float* bias = (const float*)d_in[3];
    float* out = (float*)d_out;

    int B = in_sizes[0] / NF;                    // 16384

    prep_kernel<<<(B * 64) / 256, 256>>>(x, W, bias);

    cudaFuncSetAttribute(crowds_mma_kernel,
                         cudaFuncAttributeMaxDynamicSharedMemorySize, SM_TOT);
    crowds_mma_kernel<<<(B / 128) * 2, 256, SM_TOT>>>(p, out);
}